// round 6
// baseline (speedup 1.0000x reference)
#include <cuda_runtime.h>
#include <math.h>

// Problem dims (fixed by the reference)
#define BB 128     // batch
#define TT 512     // time steps
#define DD 512     // input feature dim
#define UU 512     // GRU units
#define G3 1536    // 3*UU
#define NCTA 128   // persistent scan grid (1 CTA/SM, co-resident)
#define NGRP 4     // independent sync groups (by batch)
#define GCTA 32    // CTAs per group

// ---------------------------------------------------------------------------
// Scratch (device globals — no allocations allowed)
// ---------------------------------------------------------------------------
__device__ float g_xproj[(size_t)TT * BB * G3];   // [t][b][3U]
__device__ float g_h0[BB * UU];
__device__ float g_h1[BB * UU];
__device__ float g_rh[BB * UU];
__device__ unsigned g_flags[NCTA];                // barrier flags (zero-init)

typedef unsigned long long ull;

// Packed dual-FMA / dual-ADD (Blackwell f32x2 pipe)
#define FFMA2(acc, a, b) \
    asm("fma.rn.f32x2 %0, %1, %2, %0;" : "+l"(acc) : "l"(a), "l"(b))
#define ADD2(out, x, y) \
    asm("add.rn.f32x2 %0, %1, %2;" : "=l"(out) : "l"(x), "l"(y))
#define DUP2(out, x) \
    asm("mov.b64 %0, {%1, %1};" : "=l"(out) : "r"(__float_as_uint(x)))

__device__ __forceinline__ ull pack2(float lo, float hi)
{
    ull r;
    asm("mov.b64 %0, {%1, %2};" : "=l"(r)
        : "r"(__float_as_uint(lo)), "r"(__float_as_uint(hi)));
    return r;
}

// Flag-based group barrier: no atomics, no sleep.  Writer: release-store own
// flag = target.  Readers: lane i acquire-polls flag of group CTA i.
// Targets are monotonic (wrap-safe compare); base persists across graph
// replays via the flags themselves.
__device__ __forceinline__ void group_barrier(unsigned* flags, int self, unsigned target)
{
    __syncthreads();
    if (threadIdx.x == 0) {
        asm volatile("st.release.gpu.global.u32 [%0], %1;"
                     :: "l"(flags + self), "r"(target) : "memory");
    }
    if (threadIdx.x < GCTA) {
        const unsigned* p = flags + threadIdx.x;
        unsigned v;
        do {
            asm volatile("ld.acquire.gpu.global.u32 %0, [%1];"
                         : "=r"(v) : "l"(p) : "memory");
        } while ((int)(v - target) < 0);
    }
    __syncthreads();
}

// ---------------------------------------------------------------------------
// Kernel 1: x_proj GEMM with f32x2 packed math (unchanged — not the bottleneck)
// ---------------------------------------------------------------------------
__global__ __launch_bounds__(256) void xproj_gemm(
    const float* __restrict__ A,     // [B*T, D]
    const float* __restrict__ W,     // [D, 3U]
    const float* __restrict__ bias)  // [3U]
{
    __shared__ float As[16][132];
    __shared__ __align__(16) float Bs[16][128];

    const int tid = threadIdx.x;
    const int m0  = blockIdx.y * 128;
    const int n0  = blockIdx.x * 128;
    const int tx  = tid & 15;
    const int ty  = tid >> 4;

    ull accp[8][4];
#pragma unroll
    for (int i = 0; i < 8; i++)
#pragma unroll
        for (int j = 0; j < 4; j++) accp[i][j] = 0ull;

    for (int kc = 0; kc < DD; kc += 16) {
#pragma unroll
        for (int i = 0; i < 2; i++) {
            int id  = tid + i * 256;
            int row = id >> 2;
            int kq  = (id & 3) << 2;
            float4 v = *reinterpret_cast<const float4*>(
                &A[(size_t)(m0 + row) * DD + kc + kq]);
            As[kq + 0][row] = v.x;
            As[kq + 1][row] = v.y;
            As[kq + 2][row] = v.z;
            As[kq + 3][row] = v.w;

            int kr = id >> 5;
            int nq = (id & 31) << 2;
            float4 w = *reinterpret_cast<const float4*>(
                &W[(size_t)(kc + kr) * G3 + n0 + nq]);
            *reinterpret_cast<float4*>(&Bs[kr][nq]) = w;
        }
        __syncthreads();

#pragma unroll
        for (int k = 0; k < 16; k++) {
            float af[8];
            *reinterpret_cast<float4*>(af)     = *reinterpret_cast<float4*>(&As[k][ty * 8]);
            *reinterpret_cast<float4*>(af + 4) = *reinterpret_cast<float4*>(&As[k][ty * 8 + 4]);
            ull bfp[4];
            {
                ulonglong2 B0 = *reinterpret_cast<ulonglong2*>(&Bs[k][tx * 8]);
                ulonglong2 B1 = *reinterpret_cast<ulonglong2*>(&Bs[k][tx * 8 + 4]);
                bfp[0] = B0.x; bfp[1] = B0.y; bfp[2] = B1.x; bfp[3] = B1.y;
            }
#pragma unroll
            for (int i = 0; i < 8; i++) {
                ull ad; DUP2(ad, af[i]);
#pragma unroll
                for (int j = 0; j < 4; j++)
                    FFMA2(accp[i][j], ad, bfp[j]);
            }
        }
        __syncthreads();
    }

    float bv[8];
#pragma unroll
    for (int j = 0; j < 8; j++) bv[j] = bias[n0 + tx * 8 + j];

#pragma unroll
    for (int i = 0; i < 8; i++) {
        int m = m0 + ty * 8 + i;
        int b = m >> 9;
        int t = m & 511;
        float* dst = &g_xproj[((size_t)t * BB + b) * G3 + n0 + tx * 8];
        float c[8];
#pragma unroll
        for (int j = 0; j < 4; j++) {
            c[2 * j]     = __uint_as_float((unsigned)(accp[i][j] & 0xffffffffull));
            c[2 * j + 1] = __uint_as_float((unsigned)(accp[i][j] >> 32));
        }
        float4 o0, o1;
        o0.x = c[0] + bv[0]; o0.y = c[1] + bv[1];
        o0.z = c[2] + bv[2]; o0.w = c[3] + bv[3];
        o1.x = c[4] + bv[4]; o1.y = c[5] + bv[5];
        o1.z = c[6] + bv[6]; o1.w = c[7] + bv[7];
        *reinterpret_cast<float4*>(dst)     = o0;
        *reinterpret_cast<float4*>(dst + 4) = o1;
    }
}

// ---------------------------------------------------------------------------
// Kernel 2: persistent fused scan.  128 CTAs x 512 threads (16 warps).
// 4 independent groups of 32 CTAs; group g owns batches [32g, 32g+32) and all
// 512 units (each CTA: 32 batch x 16 units).  Barriers are group-local.
//
// SMEM (bytes):
//   hs    [32][512] f                65536
//   Rt1p  [512][17] ull (16 used)    69632   (z-pairs p<8, r-pairs p>=8)
//   Rt2p  [512][9]  ull (8 used)     36864
//   gbuf  [32][17]  ull (16 used)     4352
//   ghbuf [2][8][32] ull              4096
//   total                           180480
// ---------------------------------------------------------------------------
#define HS_F      (32 * 512)
#define RT1P_U    (512 * 17)
#define RT2P_U    (512 * 9)
#define GBUF_U    (32 * 17)
#define GHBUF_U   (2 * 8 * 32)
#define SCAN_SMEM (HS_F * 4 + (RT1P_U + RT2P_U + GBUF_U + GHBUF_U) * 8)

__global__ __launch_bounds__(512) void gru_scan(
    const float* __restrict__ R,     // [U, 3U]
    const float* __restrict__ attn,  // [B, T]
    float* __restrict__ out)         // [B, U]
{
    extern __shared__ float sm[];
    float* hs   = sm;
    ull* Rt1p   = reinterpret_cast<ull*>(sm + HS_F);
    ull* Rt2p   = Rt1p + RT1P_U;
    ull* gbuf   = Rt2p + RT2P_U;
    ull* ghbuf  = gbuf + GBUF_U;
    __shared__ unsigned s_base;

    const int tid   = threadIdx.x;
    const int cta   = blockIdx.x;
    const int group = cta >> 5;          // 4 groups of 32 CTAs
    const int gidx  = cta & 31;          // index within group
    const int b0    = group * 32;        // group owns 32 batches
    const int u0    = gidx * 16;         // CTA owns 16 units
    const int warp  = tid >> 5;
    const int lane  = tid & 31;
    unsigned* flags = g_flags + group * GCTA;

    // barrier base: all flags ended the previous launch at the same value
    if (tid == 0) s_base = flags[gidx];
    __syncthreads();
    unsigned bar = s_base;

    // ---- One-time: pack R slices into SMEM pair layouts ----
    {
        int k = tid;  // 512 threads, one k each
#pragma unroll
        for (int p = 0; p < 16; p++) {
            int col = (p < 8) ? (u0 + 2 * p) : (UU + u0 + 2 * (p - 8));
            const float* rp = &R[(size_t)k * G3 + col];
            Rt1p[k * 17 + p] = pack2(rp[0], rp[1]);
        }
#pragma unroll
        for (int p = 0; p < 8; p++) {
            const float* rp = &R[(size_t)k * G3 + 2 * UU + u0 + 2 * p];
            Rt2p[k * 9 + p] = pack2(rp[0], rp[1]);
        }
    }

    // ---- h0 = 0 ----
    {
        int eb0 = tid >> 4, eu0 = tid & 15;
        g_h0[(b0 + eb0) * UU + u0 + eu0] = 0.f;
    }
    group_barrier(flags, gidx, ++bar);

    float* hin  = g_h0;
    float* hout = g_h1;

    // phase1 warp tile ids: 4 b-blocks x 4 u-blocks of 8
    const int bw  = warp & 3;
    const int uw  = warp >> 2;
    // phase2: 4 b-blocks x 2 u-blocks x 2 k-halves
    const int bw2 = warp & 3;
    const int uw2 = (warp >> 2) & 1;
    const int kh  = warp >> 3;
    // epilogue mapping: one (b,u) element per thread
    const int eb = tid >> 4;
    const int eu = tid & 15;
    const int gb = b0 + eb;
    const int gu = u0 + eu;

    for (int t = 0; t < TT; t++) {
        // ---- prefetch this step's x_proj triple + attn (overlaps phase1) ----
        const float* xp = &g_xproj[((size_t)t * BB + gb) * G3];
        float xz = __ldg(xp + gu);
        float xr = __ldg(xp + UU + gu);
        float xh = __ldg(xp + 2 * UU + gu);
        float av = __ldg(&attn[gb * TT + t]);

        // ---- stage h rows into hs [32][512] ----
#pragma unroll
        for (int i = 0; i < 8; i++) {
            int id  = tid + i * 512;
            int row = id >> 7;
            int q   = id & 127;
            *reinterpret_cast<float4*>(&hs[row * 512 + q * 4]) =
                *reinterpret_cast<const float4*>(&hin[(b0 + row) * UU + q * 4]);
        }
        __syncthreads();

        // ======== phase 1: [32b x 512k] @ [512k x 32c]  (c = z|r) ========
        ull acc[8][4];
#pragma unroll
        for (int i = 0; i < 8; i++)
#pragma unroll
            for (int p = 0; p < 4; p++) acc[i][p] = 0ull;

        {
            const float* ap = hs + (bw * 8) * 512 + lane;
            const ull*   wp = Rt1p + lane * 17 + uw * 4;
#pragma unroll 4
            for (int j = 0; j < 16; j++) {
                ull w[4];
#pragma unroll
                for (int p = 0; p < 4; p++) w[p] = wp[p];
                wp += 32 * 17;
#pragma unroll
                for (int i = 0; i < 8; i++) {
                    float a = ap[i * 512 + j * 32];
                    ull ad; DUP2(ad, a);
#pragma unroll
                    for (int p = 0; p < 4; p++)
                        FFMA2(acc[i][p], ad, w[p]);
                }
            }
        }

        // butterfly reduction over lanes; lane l ends owning flat idx l
        {
            ull* v = &acc[0][0];
#pragma unroll
            for (int d = 16; d >= 1; d >>= 1) {
                bool hi = (lane & d) != 0;
#pragma unroll
                for (int i = 0; i < 32; i++) {
                    if (i >= d) break;
                    ull send = hi ? v[i] : v[i + d];
                    ull recv = __shfl_xor_sync(0xffffffffu, send, d);
                    ull keep = hi ? v[i + d] : v[i];
                    ADD2(v[i], keep, recv);
                }
            }
            gbuf[(bw * 8 + (lane >> 2)) * 17 + uw * 4 + (lane & 3)] = v[0];
        }
        __syncthreads();

        // ---- epilogue 1: z, r; write rh ----
        const float* gf = reinterpret_cast<const float*>(gbuf);  // row stride 34
        float gz = gf[eb * 34 + eu];
        float gr = gf[eb * 34 + 16 + eu];
        float z = fminf(fmaxf(0.2f * (xz + gz) + 0.5f, 0.f), 1.f);
        float r = fminf(fmaxf(0.2f * (xr + gr) + 0.5f, 0.f), 1.f);
        float hold = hs[eb * 512 + gu];
        g_rh[gb * UU + gu] = r * hold;
        group_barrier(flags, gidx, ++bar);   // all rh visible in group

        // ---- stage rh into hs ----
#pragma unroll
        for (int i = 0; i < 8; i++) {
            int id  = tid + i * 512;
            int row = id >> 7;
            int q   = id & 127;
            *reinterpret_cast<float4*>(&hs[row * 512 + q * 4]) =
                *reinterpret_cast<const float4*>(&g_rh[(b0 + row) * UU + q * 4]);
        }
        __syncthreads();

        // ======== phase 2: [32b x 512k] @ [512k x 16u], k split 2 ways ========
        ull acc2[8][4];
#pragma unroll
        for (int i = 0; i < 8; i++)
#pragma unroll
            for (int p = 0; p < 4; p++) acc2[i][p] = 0ull;

        {
            const float* ap = hs + (bw2 * 8) * 512 + kh * 256 + lane;
            const ull*   wp = Rt2p + (kh * 256 + lane) * 9 + uw2 * 4;
#pragma unroll 4
            for (int j = 0; j < 8; j++) {
                ull w[4];
#pragma unroll
                for (int p = 0; p < 4; p++) w[p] = wp[p];
                wp += 32 * 9;
#pragma unroll
                for (int i = 0; i < 8; i++) {
                    float a = ap[i * 512 + j * 32];
                    ull ad; DUP2(ad, a);
#pragma unroll
                    for (int p = 0; p < 4; p++)
                        FFMA2(acc2[i][p], ad, w[p]);
                }
            }
        }

        {
            ull* v = &acc2[0][0];
#pragma unroll
            for (int d = 16; d >= 1; d >>= 1) {
                bool hi = (lane & d) != 0;
#pragma unroll
                for (int i = 0; i < 32; i++) {
                    if (i >= d) break;
                    ull send = hi ? v[i] : v[i + d];
                    ull recv = __shfl_xor_sync(0xffffffffu, send, d);
                    ull keep = hi ? v[i + d] : v[i];
                    ADD2(v[i], keep, recv);
                }
            }
            int tile = uw2 * 4 + bw2;
            ghbuf[kh * 256 + tile * 32 + lane] = v[0];
        }
        __syncthreads();

        // ---- epilogue 2: hh, state update, attn blend ----
        {
            int bt   = eb >> 3;
            int ut   = eu >> 3;
            int tile = ut * 4 + bt;
            int li   = (eb & 7) * 4 + ((eu >> 1) & 3);
            const float* ghf = reinterpret_cast<const float*>(ghbuf);
            float gh = ghf[(tile * 32 + li) * 2 + (eu & 1)]
                     + ghf[(256 + tile * 32 + li) * 2 + (eu & 1)];
            float hh = tanhf(xh + gh);
            float hn = z * hold + (1.f - z) * hh;
            float ho = av * hn + (1.f - av) * hold;
            if (t == TT - 1) out[gb * UU + gu] = ho;
            else             hout[gb * UU + gu] = ho;
        }
        group_barrier(flags, gidx, ++bar);   // all h visible in group

        float* tmp = hin; hin = hout; hout = tmp;
    }
}

// ---------------------------------------------------------------------------
// Host launcher: 2 kernel nodes
// ---------------------------------------------------------------------------
extern "C" void kernel_launch(void* const* d_in, const int* in_sizes, int n_in,
                              void* d_out, int out_size)
{
    (void)in_sizes; (void)n_in; (void)out_size;
    const float* inputs = (const float*)d_in[0];  // [B,T,D]
    const float* attn   = (const float*)d_in[1];  // [B,T,1]
    const float* W      = (const float*)d_in[2];  // [D,3U]
    const float* R      = (const float*)d_in[3];  // [U,3U]
    const float* bias   = (const float*)d_in[4];  // [3U]
    float* out = (float*)d_out;                   // [B,U]

    static int smem_set = 0;
    if (!smem_set) {
        cudaFuncSetAttribute(gru_scan, cudaFuncAttributeMaxDynamicSharedMemorySize, SCAN_SMEM);
        smem_set = 1;
    }

    dim3 ggrid(G3 / 128, (BB * TT) / 128);
    xproj_gemm<<<ggrid, 256>>>(inputs, W, bias);

    gru_scan<<<NCTA, 512, SCAN_SMEM>>>(R, attn, out);
}

// round 8
// speedup vs baseline: 1.0323x; 1.0323x over previous
#include <cuda_runtime.h>
#include <math.h>

// Problem dims (fixed by the reference)
#define BB 128     // batch
#define TT 512     // time steps
#define DD 512     // input feature dim
#define UU 512     // GRU units
#define G3 1536    // 3*UU
#define NCTA 128   // persistent scan grid (1 CTA/SM, co-resident)
#define NGRP 4     // independent sync groups (by 32-batch slice)
#define GCTA 32    // CTAs per group

// ---------------------------------------------------------------------------
// Scratch (device globals — no allocations allowed)
// ---------------------------------------------------------------------------
__device__ float g_xproj[(size_t)TT * BB * G3];   // [t][b][3U]
__device__ float g_h0[BB * UU];
__device__ float g_h1[BB * UU];
__device__ float g_rh[BB * UU];
__device__ unsigned g_cnt[NGRP][2];               // per (group, half) counters
__device__ volatile unsigned g_gen[NGRP][2];      // per (group, half) generations

typedef unsigned long long ull;

// Packed dual-FMA / dual-ADD (Blackwell f32x2 pipe)
#define FFMA2(acc, a, b) \
    asm("fma.rn.f32x2 %0, %1, %2, %0;" : "+l"(acc) : "l"(a), "l"(b))
#define ADD2(out, x, y) \
    asm("add.rn.f32x2 %0, %1, %2;" : "=l"(out) : "l"(x), "l"(y))
#define DUP2(out, x) \
    asm("mov.b64 %0, {%1, %1};" : "=l"(out) : "r"(__float_as_uint(x)))

__device__ __forceinline__ ull pack2(float lo, float hi)
{
    ull r;
    asm("mov.b64 %0, {%1, %2};" : "=l"(r)
        : "r"(__float_as_uint(lo)), "r"(__float_as_uint(hi)));
    return r;
}

// Split-phase group barrier (proven R5 mechanism: atomicAdd + gen + nanosleep).
// arrive: all threads sync, thread0 fences and adds; the 32nd arrival resets
// the counter and bumps the generation.  wait: thread0 polls the generation
// (monotonic target, wrap-safe), then the CTA syncs.
__device__ __forceinline__ void bar_arrive(int grp, int h)
{
    __syncthreads();
    if (threadIdx.x == 0) {
        __threadfence();
        if (atomicAdd(&g_cnt[grp][h], 1u) == GCTA - 1) {
            g_cnt[grp][h] = 0;
            __threadfence();
            g_gen[grp][h] = g_gen[grp][h] + 1;
        }
    }
}
__device__ __forceinline__ void bar_wait(int grp, int h, unsigned target)
{
    if (threadIdx.x == 0) {
        while ((int)(g_gen[grp][h] - target) < 0) { __nanosleep(32); }
        __threadfence();
    }
    __syncthreads();
}

// ---------------------------------------------------------------------------
// Kernel 1: x_proj GEMM with f32x2 packed math (unchanged from R4/R5).
// ---------------------------------------------------------------------------
__global__ __launch_bounds__(256) void xproj_gemm(
    const float* __restrict__ A,     // [B*T, D]
    const float* __restrict__ W,     // [D, 3U]
    const float* __restrict__ bias)  // [3U]
{
    __shared__ float As[16][132];
    __shared__ __align__(16) float Bs[16][128];

    const int tid = threadIdx.x;
    const int m0  = blockIdx.y * 128;
    const int n0  = blockIdx.x * 128;
    const int tx  = tid & 15;
    const int ty  = tid >> 4;

    ull accp[8][4];
#pragma unroll
    for (int i = 0; i < 8; i++)
#pragma unroll
        for (int j = 0; j < 4; j++) accp[i][j] = 0ull;

    for (int kc = 0; kc < DD; kc += 16) {
#pragma unroll
        for (int i = 0; i < 2; i++) {
            int id  = tid + i * 256;
            int row = id >> 2;
            int kq  = (id & 3) << 2;
            float4 v = *reinterpret_cast<const float4*>(
                &A[(size_t)(m0 + row) * DD + kc + kq]);
            As[kq + 0][row] = v.x;
            As[kq + 1][row] = v.y;
            As[kq + 2][row] = v.z;
            As[kq + 3][row] = v.w;

            int kr = id >> 5;
            int nq = (id & 31) << 2;
            float4 w = *reinterpret_cast<const float4*>(
                &W[(size_t)(kc + kr) * G3 + n0 + nq]);
            *reinterpret_cast<float4*>(&Bs[kr][nq]) = w;
        }
        __syncthreads();

#pragma unroll
        for (int k = 0; k < 16; k++) {
            float af[8];
            *reinterpret_cast<float4*>(af)     = *reinterpret_cast<float4*>(&As[k][ty * 8]);
            *reinterpret_cast<float4*>(af + 4) = *reinterpret_cast<float4*>(&As[k][ty * 8 + 4]);
            ull bfp[4];
            {
                ulonglong2 B0 = *reinterpret_cast<ulonglong2*>(&Bs[k][tx * 8]);
                ulonglong2 B1 = *reinterpret_cast<ulonglong2*>(&Bs[k][tx * 8 + 4]);
                bfp[0] = B0.x; bfp[1] = B0.y; bfp[2] = B1.x; bfp[3] = B1.y;
            }
#pragma unroll
            for (int i = 0; i < 8; i++) {
                ull ad; DUP2(ad, af[i]);
#pragma unroll
                for (int j = 0; j < 4; j++)
                    FFMA2(accp[i][j], ad, bfp[j]);
            }
        }
        __syncthreads();
    }

    float bv[8];
#pragma unroll
    for (int j = 0; j < 8; j++) bv[j] = bias[n0 + tx * 8 + j];

#pragma unroll
    for (int i = 0; i < 8; i++) {
        int m = m0 + ty * 8 + i;
        int b = m >> 9;
        int t = m & 511;
        float* dst = &g_xproj[((size_t)t * BB + b) * G3 + n0 + tx * 8];
        float c[8];
#pragma unroll
        for (int j = 0; j < 4; j++) {
            c[2 * j]     = __uint_as_float((unsigned)(accp[i][j] & 0xffffffffull));
            c[2 * j + 1] = __uint_as_float((unsigned)(accp[i][j] >> 32));
        }
        float4 o0, o1;
        o0.x = c[0] + bv[0]; o0.y = c[1] + bv[1];
        o0.z = c[2] + bv[2]; o0.w = c[3] + bv[3];
        o1.x = c[4] + bv[4]; o1.y = c[5] + bv[5];
        o1.z = c[6] + bv[6]; o1.w = c[7] + bv[7];
        *reinterpret_cast<float4*>(dst)     = o0;
        *reinterpret_cast<float4*>(dst + 4) = o1;
    }
}

// ---------------------------------------------------------------------------
// Kernel 2: persistent fused scan, batch-half software pipelining.
// 128 CTAs x 512 threads.  Group g (32 CTAs) owns batches [32g, 32g+32);
// CTA gidx owns units [16*gidx, 16*gidx+16).  Each step processes two
// 16-batch halves (alpha rows 0-15 of hs, beta rows 16-31) with separate
// barrier objects; each barrier wait is hidden behind the other half's work.
//
// SMEM: hs[32][512]f 65536 | Rt1p[512][17]ull 69632 | Rt2p[512][9]ull 36864
//       gbuf[2*16][17]ull 4352 | ghbuf[16][32]ull 4096   = 180480 B
// ---------------------------------------------------------------------------
#define HS_F      (32 * 512)
#define RT1P_U    (512 * 17)
#define RT2P_U    (512 * 9)
#define GBUF_U    (2 * 16 * 17)
#define GHBUF_U   (16 * 32)
#define SCAN_SMEM (HS_F * 4 + (RT1P_U + RT2P_U + GBUF_U + GHBUF_U) * 8)

// ---- 16-row staging: hs rows [HB, HB+16) <- src rows [b0+HB, b0+HB+16) ----
#define STAGE16(HB, SRC) do {                                                 \
    _Pragma("unroll")                                                         \
    for (int i_ = 0; i_ < 4; i_++) {                                          \
        int id_  = tid + i_ * 512;                                            \
        int row_ = id_ >> 7;                                                  \
        int q_   = id_ & 127;                                                 \
        *reinterpret_cast<float4*>(&hs[((HB) + row_) * 512 + q_ * 4]) =       \
            *reinterpret_cast<const float4*>(&(SRC)[(b0 + (HB) + row_) * UU + q_ * 4]); \
    }                                                                         \
    __syncthreads();                                                          \
} while (0)

// ---- butterfly reduction of 32 ull accumulators over the warp ----
#define BUTTERFLY(ACC) do {                                                   \
    ull* v_ = &(ACC)[0][0];                                                   \
    _Pragma("unroll")                                                         \
    for (int d_ = 16; d_ >= 1; d_ >>= 1) {                                    \
        bool hi_ = (lane & d_) != 0;                                          \
        _Pragma("unroll")                                                     \
        for (int i_ = 0; i_ < 32; i_++) {                                     \
            if (i_ >= d_) break;                                              \
            ull send_ = hi_ ? v_[i_] : v_[i_ + d_];                           \
            ull recv_ = __shfl_xor_sync(0xffffffffu, send_, d_);              \
            ull keep_ = hi_ ? v_[i_ + d_] : v_[i_];                           \
            ADD2(v_[i_], keep_, recv_);                                       \
        }                                                                     \
    }                                                                         \
} while (0)

// ---- phase 1 for half at hs-row base HB: 16b x 32c (z|r), k 2-way split ----
#define PHASE1(HB) do {                                                       \
    ull acc[8][4];                                                            \
    _Pragma("unroll")                                                         \
    for (int i_ = 0; i_ < 8; i_++)                                            \
        _Pragma("unroll")                                                     \
        for (int p_ = 0; p_ < 4; p_++) acc[i_][p_] = 0ull;                    \
    const float* ap_ = hs + ((HB) + bw1 * 8) * 512;                           \
    _Pragma("unroll")                                                         \
    for (int j_ = 0; j_ < 8; j_++) {                                          \
        int k_ = kh1 * 256 + j_ * 32 + lane;                                  \
        const ull* wp_ = Rt1p + k_ * 17 + uw1 * 4;                            \
        ull w0_ = wp_[0], w1_ = wp_[1], w2_ = wp_[2], w3_ = wp_[3];           \
        _Pragma("unroll")                                                     \
        for (int i_ = 0; i_ < 8; i_++) {                                      \
            float a_ = ap_[i_ * 512 + k_];                                    \
            ull ad_; DUP2(ad_, a_);                                           \
            FFMA2(acc[i_][0], ad_, w0_);                                      \
            FFMA2(acc[i_][1], ad_, w1_);                                      \
            FFMA2(acc[i_][2], ad_, w2_);                                      \
            FFMA2(acc[i_][3], ad_, w3_);                                      \
        }                                                                     \
    }                                                                         \
    BUTTERFLY(acc);                                                           \
    gbuf[(kh1 * 16 + bw1 * 8 + (lane >> 2)) * 17 + uw1 * 4 + (lane & 3)] =    \
        acc[0][0];                                                            \
    __syncthreads();                                                          \
} while (0)

// ---- phase 2 for half at hs-row base HB: 16b x 16u, k 4-way split ----
#define PHASE2(HB) do {                                                       \
    ull acc[8][4];                                                            \
    _Pragma("unroll")                                                         \
    for (int i_ = 0; i_ < 8; i_++)                                            \
        _Pragma("unroll")                                                     \
        for (int p_ = 0; p_ < 4; p_++) acc[i_][p_] = 0ull;                    \
    const float* ap_ = hs + ((HB) + bw2 * 8) * 512;                           \
    _Pragma("unroll")                                                         \
    for (int j_ = 0; j_ < 4; j_++) {                                          \
        int k_ = kh2 * 128 + j_ * 32 + lane;                                  \
        const ull* wp_ = Rt2p + k_ * 9 + uw2 * 4;                             \
        ull w0_ = wp_[0], w1_ = wp_[1], w2_ = wp_[2], w3_ = wp_[3];           \
        _Pragma("unroll")                                                     \
        for (int i_ = 0; i_ < 8; i_++) {                                      \
            float a_ = ap_[i_ * 512 + k_];                                    \
            ull ad_; DUP2(ad_, a_);                                           \
            FFMA2(acc[i_][0], ad_, w0_);                                      \
            FFMA2(acc[i_][1], ad_, w1_);                                      \
            FFMA2(acc[i_][2], ad_, w2_);                                      \
            FFMA2(acc[i_][3], ad_, w3_);                                      \
        }                                                                     \
    }                                                                         \
    BUTTERFLY(acc);                                                           \
    ghbuf[(kh2 * 4 + uw2 * 2 + bw2) * 32 + lane] = acc[0][0];                 \
    __syncthreads();                                                          \
} while (0)

__global__ __launch_bounds__(512) void gru_scan(
    const float* __restrict__ R,     // [U, 3U]
    const float* __restrict__ attn,  // [B, T]
    float* __restrict__ out)         // [B, U]
{
    extern __shared__ float sm[];
    float* hs  = sm;
    ull* Rt1p  = reinterpret_cast<ull*>(sm + HS_F);
    ull* Rt2p  = Rt1p + RT1P_U;
    ull* gbuf  = Rt2p + RT2P_U;
    ull* ghbuf = gbuf + GBUF_U;
    __shared__ unsigned s_base[2];

    const int tid   = threadIdx.x;
    const int cta   = blockIdx.x;
    const int group = cta >> 5;
    const int gidx  = cta & 31;
    const int b0    = group * 32;
    const int u0    = gidx * 16;
    const int warp  = tid >> 5;
    const int lane  = tid & 31;

    // barrier bases (safe: no arrive can release before all 32 CTAs arrive)
    if (tid == 0) {
        s_base[0] = g_gen[group][0];
        s_base[1] = g_gen[group][1];
    }
    __syncthreads();
    unsigned next0 = s_base[0], next1 = s_base[1];

    // ---- One-time: pack R slices into SMEM pair layouts (resident) ----
    {
        int k = tid;
#pragma unroll
        for (int p = 0; p < 16; p++) {
            int col = (p < 8) ? (u0 + 2 * p) : (UU + u0 + 2 * (p - 8));
            const float* rp = &R[(size_t)k * G3 + col];
            Rt1p[k * 17 + p] = pack2(rp[0], rp[1]);
        }
#pragma unroll
        for (int p = 0; p < 8; p++) {
            const float* rp = &R[(size_t)k * G3 + 2 * UU + u0 + 2 * p];
            Rt2p[k * 9 + p] = pack2(rp[0], rp[1]);
        }
    }

    // ---- h0 = 0 (full 32-batch tile) ----
    {
        int zb = tid >> 4, zu = tid & 15;
        g_h0[(b0 + zb) * UU + u0 + zu] = 0.f;
    }
    bar_arrive(group, 0);  unsigned pB0 = ++next0;   // "B-event" of step -1
    bar_arrive(group, 1);  unsigned pB1 = ++next1;

    float* hin  = g_h0;
    float* hout = g_h1;

    // warp tiling ids
    const int kh1 = warp >> 3;         // phase1: 2-way k split
    const int bw1 = warp & 1;
    const int uw1 = (warp >> 1) & 3;
    const int kh2 = warp >> 2;         // phase2: 4-way k split
    const int bw2 = warp & 1;
    const int uw2 = (warp >> 1) & 1;
    // epilogue element (threads 0-255): one (b,u) of the 16x16 half tile
    const int eb = (tid >> 4) & 15;
    const int eu = tid & 15;
    const int gu = u0 + eu;

    unsigned pA0, pA1;
    float zA = 0.f, holdA = 0.f, xhA = 0.f, avA = 0.f;
    float zB = 0.f, holdB = 0.f, xhB = 0.f, avB = 0.f;

    for (int t = 0; t < TT; t++) {
        // ================= half A : phase 1 =================
        float xzA = 0.f, xrA = 0.f;
        if (tid < 256) {                    // prefetch before the wait
            const float* xp = &g_xproj[((size_t)t * BB + b0 + eb) * G3];
            xzA = __ldg(xp + gu);
            xrA = __ldg(xp + UU + gu);
            xhA = __ldg(xp + 2 * UU + gu);
            avA = __ldg(&attn[(b0 + eb) * TT + t]);
        }
        bar_wait(group, 0, pB0);            // h(t-1) of half A visible
        STAGE16(0, hin);
        PHASE1(0);
        if (tid < 256) {
            const float* gF = reinterpret_cast<const float*>(gbuf);
            float gz = gF[eb * 34 + eu]      + gF[(16 + eb) * 34 + eu];
            float gr = gF[eb * 34 + 16 + eu] + gF[(16 + eb) * 34 + 16 + eu];
            zA = fminf(fmaxf(0.2f * (xzA + gz) + 0.5f, 0.f), 1.f);
            float r = fminf(fmaxf(0.2f * (xrA + gr) + 0.5f, 0.f), 1.f);
            holdA = hs[eb * 512 + gu];
            g_rh[(b0 + eb) * UU + gu] = r * holdA;
        }
        bar_arrive(group, 0);  pA0 = ++next0;

        // ================= half B : phase 1 =================
        float xzB = 0.f, xrB = 0.f;
        if (tid < 256) {
            const float* xp = &g_xproj[((size_t)t * BB + b0 + 16 + eb) * G3];
            xzB = __ldg(xp + gu);
            xrB = __ldg(xp + UU + gu);
            xhB = __ldg(xp + 2 * UU + gu);
            avB = __ldg(&attn[(b0 + 16 + eb) * TT + t]);
        }
        bar_wait(group, 1, pB1);
        STAGE16(16, hin);
        PHASE1(16);
        if (tid < 256) {
            const float* gF = reinterpret_cast<const float*>(gbuf);
            float gz = gF[eb * 34 + eu]      + gF[(16 + eb) * 34 + eu];
            float gr = gF[eb * 34 + 16 + eu] + gF[(16 + eb) * 34 + 16 + eu];
            zB = fminf(fmaxf(0.2f * (xzB + gz) + 0.5f, 0.f), 1.f);
            float r = fminf(fmaxf(0.2f * (xrB + gr) + 0.5f, 0.f), 1.f);
            holdB = hs[(16 + eb) * 512 + gu];
            g_rh[(b0 + 16 + eb) * UU + gu] = r * holdB;
        }
        bar_arrive(group, 1);  pA1 = ++next1;

        // ================= half A : phase 2 =================
        bar_wait(group, 0, pA0);            // rh of half A visible
        STAGE16(0, g_rh);
        PHASE2(0);
        if (tid < 256) {
            int tile = (eu >> 3) * 2 + (eb >> 3);
            int li   = (eb & 7) * 4 + ((eu >> 1) & 3);
            const float* ghF = reinterpret_cast<const float*>(ghbuf);
            float gh = 0.f;
#pragma unroll
            for (int kk = 0; kk < 4; kk++)
                gh += ghF[((kk * 4 + tile) * 32 + li) * 2 + (eu & 1)];
            float hh = tanhf(xhA + gh);
            float hn = zA * holdA + (1.f - zA) * hh;
            float ho = avA * hn + (1.f - avA) * holdA;
            float* dst = (t == TT - 1) ? out : hout;
            dst[(b0 + eb) * UU + gu] = ho;
        }
        bar_arrive(group, 0);  pB0 = ++next0;

        // ================= half B : phase 2 =================
        bar_wait(group, 1, pA1);
        STAGE16(16, g_rh);
        PHASE2(16);
        if (tid < 256) {
            int tile = (eu >> 3) * 2 + (eb >> 3);
            int li   = (eb & 7) * 4 + ((eu >> 1) & 3);
            const float* ghF = reinterpret_cast<const float*>(ghbuf);
            float gh = 0.f;
#pragma unroll
            for (int kk = 0; kk < 4; kk++)
                gh += ghF[((kk * 4 + tile) * 32 + li) * 2 + (eu & 1)];
            float hh = tanhf(xhB + gh);
            float hn = zB * holdB + (1.f - zB) * hh;
            float ho = avB * hn + (1.f - avB) * holdB;
            float* dst = (t == TT - 1) ? out : hout;
            dst[(b0 + 16 + eb) * UU + gu] = ho;
        }
        bar_arrive(group, 1);  pB1 = ++next1;

        float* tmp = hin; hin = hout; hout = tmp;
    }
}

// ---------------------------------------------------------------------------
// Host launcher: 2 kernel nodes
// ---------------------------------------------------------------------------
extern "C" void kernel_launch(void* const* d_in, const int* in_sizes, int n_in,
                              void* d_out, int out_size)
{
    (void)in_sizes; (void)n_in; (void)out_size;
    const float* inputs = (const float*)d_in[0];  // [B,T,D]
    const float* attn   = (const float*)d_in[1];  // [B,T,1]
    const float* W      = (const float*)d_in[2];  // [D,3U]
    const float* R      = (const float*)d_in[3];  // [U,3U]
    const float* bias   = (const float*)d_in[4];  // [3U]
    float* out = (float*)d_out;                   // [B,U]

    static int smem_set = 0;
    if (!smem_set) {
        cudaFuncSetAttribute(gru_scan, cudaFuncAttributeMaxDynamicSharedMemorySize, SCAN_SMEM);
        smem_set = 1;
    }

    dim3 ggrid(G3 / 128, (BB * TT) / 128);
    xproj_gemm<<<ggrid, 256>>>(inputs, W, bias);

    gru_scan<<<NCTA, 512, SCAN_SMEM>>>(R, attn, out);
}

// round 9
// speedup vs baseline: 1.4930x; 1.4463x over previous
#include <cuda_runtime.h>
#include <math.h>

// Problem dims (fixed by the reference)
#define BB 128     // batch
#define TT 512     // time steps
#define DD 512     // input feature dim
#define UU 512     // GRU units
#define G3 1536    // 3*UU
#define NCTA 128   // persistent scan grid (1 CTA/SM, co-resident)
#define NGRP 4     // independent sync groups (one per 32-batch slice)
#define GCTA 32    // CTAs per group

// ---------------------------------------------------------------------------
// Scratch (device globals — no allocations allowed)
// ---------------------------------------------------------------------------
__device__ float g_xproj[(size_t)TT * BB * G3];   // [t][b][3U]
__device__ float g_h0[BB * UU];
__device__ float g_h1[BB * UU];
__device__ float g_rh[BB * UU];
__device__ unsigned g_cnt[NGRP];                  // per-group counters
__device__ volatile unsigned g_gen[NGRP];         // per-group generations

typedef unsigned long long ull;

// Packed dual-FMA / dual-ADD (Blackwell f32x2 pipe)
#define FFMA2(acc, a, b) \
    asm("fma.rn.f32x2 %0, %1, %2, %0;" : "+l"(acc) : "l"(a), "l"(b))
#define ADD2(out, x, y) \
    asm("add.rn.f32x2 %0, %1, %2;" : "=l"(out) : "l"(x), "l"(y))
#define DUP2(out, x) \
    asm("mov.b64 %0, {%1, %1};" : "=l"(out) : "r"(__float_as_uint(x)))

__device__ __forceinline__ ull pack2(float lo, float hi)
{
    ull r;
    asm("mov.b64 %0, {%1, %2};" : "=l"(r)
        : "r"(__float_as_uint(lo)), "r"(__float_as_uint(hi)));
    return r;
}

// Proven R5 barrier mechanism (atomicAdd + generation + nanosleep), scoped to
// a 32-CTA group: arrival serialization drops 128->32 concurrent atomics.
__device__ __forceinline__ void group_barrier(int grp)
{
    __syncthreads();
    if (threadIdx.x == 0) {
        __threadfence();
        unsigned gen = g_gen[grp];
        if (atomicAdd(&g_cnt[grp], 1u) == GCTA - 1) {
            g_cnt[grp] = 0;
            __threadfence();
            g_gen[grp] = gen + 1;
        } else {
            while (g_gen[grp] == gen) { __nanosleep(32); }
        }
        __threadfence();
    }
    __syncthreads();
}

// ---------------------------------------------------------------------------
// Kernel 1: x_proj GEMM with f32x2 packed math (unchanged from R4/R5).
// ---------------------------------------------------------------------------
__global__ __launch_bounds__(256) void xproj_gemm(
    const float* __restrict__ A,     // [B*T, D]
    const float* __restrict__ W,     // [D, 3U]
    const float* __restrict__ bias)  // [3U]
{
    __shared__ float As[16][132];
    __shared__ __align__(16) float Bs[16][128];

    const int tid = threadIdx.x;
    const int m0  = blockIdx.y * 128;
    const int n0  = blockIdx.x * 128;
    const int tx  = tid & 15;
    const int ty  = tid >> 4;

    ull accp[8][4];
#pragma unroll
    for (int i = 0; i < 8; i++)
#pragma unroll
        for (int j = 0; j < 4; j++) accp[i][j] = 0ull;

    for (int kc = 0; kc < DD; kc += 16) {
#pragma unroll
        for (int i = 0; i < 2; i++) {
            int id  = tid + i * 256;
            int row = id >> 2;
            int kq  = (id & 3) << 2;
            float4 v = *reinterpret_cast<const float4*>(
                &A[(size_t)(m0 + row) * DD + kc + kq]);
            As[kq + 0][row] = v.x;
            As[kq + 1][row] = v.y;
            As[kq + 2][row] = v.z;
            As[kq + 3][row] = v.w;

            int kr = id >> 5;
            int nq = (id & 31) << 2;
            float4 w = *reinterpret_cast<const float4*>(
                &W[(size_t)(kc + kr) * G3 + n0 + nq]);
            *reinterpret_cast<float4*>(&Bs[kr][nq]) = w;
        }
        __syncthreads();

#pragma unroll
        for (int k = 0; k < 16; k++) {
            float af[8];
            *reinterpret_cast<float4*>(af)     = *reinterpret_cast<float4*>(&As[k][ty * 8]);
            *reinterpret_cast<float4*>(af + 4) = *reinterpret_cast<float4*>(&As[k][ty * 8 + 4]);
            ull bfp[4];
            {
                ulonglong2 B0 = *reinterpret_cast<ulonglong2*>(&Bs[k][tx * 8]);
                ulonglong2 B1 = *reinterpret_cast<ulonglong2*>(&Bs[k][tx * 8 + 4]);
                bfp[0] = B0.x; bfp[1] = B0.y; bfp[2] = B1.x; bfp[3] = B1.y;
            }
#pragma unroll
            for (int i = 0; i < 8; i++) {
                ull ad; DUP2(ad, af[i]);
#pragma unroll
                for (int j = 0; j < 4; j++)
                    FFMA2(accp[i][j], ad, bfp[j]);
            }
        }
        __syncthreads();
    }

    float bv[8];
#pragma unroll
    for (int j = 0; j < 8; j++) bv[j] = bias[n0 + tx * 8 + j];

#pragma unroll
    for (int i = 0; i < 8; i++) {
        int m = m0 + ty * 8 + i;
        int b = m >> 9;
        int t = m & 511;
        float* dst = &g_xproj[((size_t)t * BB + b) * G3 + n0 + tx * 8];
        float c[8];
#pragma unroll
        for (int j = 0; j < 4; j++) {
            c[2 * j]     = __uint_as_float((unsigned)(accp[i][j] & 0xffffffffull));
            c[2 * j + 1] = __uint_as_float((unsigned)(accp[i][j] >> 32));
        }
        float4 o0, o1;
        o0.x = c[0] + bv[0]; o0.y = c[1] + bv[1];
        o0.z = c[2] + bv[2]; o0.w = c[3] + bv[3];
        o1.x = c[4] + bv[4]; o1.y = c[5] + bv[5];
        o1.z = c[6] + bv[6]; o1.w = c[7] + bv[7];
        *reinterpret_cast<float4*>(dst)     = o0;
        *reinterpret_cast<float4*>(dst + 4) = o1;
    }
}

// ---------------------------------------------------------------------------
// Kernel 2: persistent fused scan (R5 structure; group-scoped barriers).
// 128 CTAs x 512 threads.  CTA (cta&3 -> 32-batch slice, cta>>2 -> 16-unit
// slice).  group = cta&3 — all CTAs sharing a batch slice sync together.
//
// SMEM floats: hs 32*512 | Rt1p 512*17 ull | Rt2p 512*9 ull | gbuf | ghbuf
// ---------------------------------------------------------------------------
#define HS_F      (32 * 512)
#define RT1P_U    (512 * 17)
#define RT2P_U    (512 * 9)
#define GBUF_U    (32 * 17)
#define GHBUF_U   (2 * 8 * 32)
#define SCAN_SMEM (HS_F * 4 + (RT1P_U + RT2P_U + GBUF_U + GHBUF_U) * 8)

__global__ __launch_bounds__(512) void gru_scan(
    const float* __restrict__ R,     // [U, 3U]
    const float* __restrict__ attn,  // [B, T]
    float* __restrict__ out)         // [B, U]
{
    extern __shared__ float sm[];
    float* hs   = sm;
    ull* Rt1p   = reinterpret_cast<ull*>(sm + HS_F);
    ull* Rt2p   = Rt1p + RT1P_U;
    ull* gbuf   = Rt2p + RT2P_U;
    ull* ghbuf  = gbuf + GBUF_U;

    const int tid   = threadIdx.x;
    const int cta   = blockIdx.x;
    const int group = cta & 3;           // batch-slice group (32 CTAs)
    const int b0    = group * 32;
    const int u0    = (cta >> 2) * 16;
    const int warp  = tid >> 5;
    const int lane  = tid & 31;

    // ---- One-time: pack R slices into SMEM pair layouts (resident) ----
    {
        int k = tid;  // 512 threads, one k each
#pragma unroll
        for (int p = 0; p < 16; p++) {
            int col = (p < 8) ? (u0 + 2 * p) : (UU + u0 + 2 * (p - 8));
            const float* rp = &R[(size_t)k * G3 + col];
            Rt1p[k * 17 + p] = pack2(rp[0], rp[1]);
        }
#pragma unroll
        for (int p = 0; p < 8; p++) {
            const float* rp = &R[(size_t)k * G3 + 2 * UU + u0 + 2 * p];
            Rt2p[k * 9 + p] = pack2(rp[0], rp[1]);
        }
    }

    // ---- h0 = 0 ----
    {
        int zb = tid >> 4, zu = tid & 15;
        g_h0[(b0 + zb) * UU + u0 + zu] = 0.f;
    }
    group_barrier(group);

    float* hin  = g_h0;
    float* hout = g_h1;

    // phase1 warp tile ids: 4 b-blocks x 4 u-blocks of 8
    const int bw  = warp & 3;
    const int uw  = warp >> 2;
    // phase2: 4 b-blocks x 2 u-blocks x 2 k-halves
    const int bw2 = warp & 3;
    const int uw2 = (warp >> 2) & 1;
    const int kh  = warp >> 3;
    // epilogue mapping: one (b,u) element per thread
    const int eb = tid >> 4;
    const int eu = tid & 15;
    const int gb = b0 + eb;
    const int gu = u0 + eu;

    for (int t = 0; t < TT; t++) {
        // ---- prefetch this step's x_proj triple + attn (barrier-independent) ----
        const float* xp = &g_xproj[((size_t)t * BB + gb) * G3];
        float xz = __ldg(xp + gu);
        float xr = __ldg(xp + UU + gu);
        float xh = __ldg(xp + 2 * UU + gu);
        float av = __ldg(&attn[gb * TT + t]);

        // ---- stage h rows into hs [32][512] ----
#pragma unroll
        for (int i = 0; i < 8; i++) {
            int id  = tid + i * 512;
            int row = id >> 7;
            int q   = id & 127;
            *reinterpret_cast<float4*>(&hs[row * 512 + q * 4]) =
                *reinterpret_cast<const float4*>(&hin[(b0 + row) * UU + q * 4]);
        }
        __syncthreads();

        // ======== phase 1: [32b x 512k] @ [512k x 32c]  (c = z|r) ========
        ull acc[8][4];
#pragma unroll
        for (int i = 0; i < 8; i++)
#pragma unroll
            for (int p = 0; p < 4; p++) acc[i][p] = 0ull;

        {
            const float* ap = hs + (bw * 8) * 512 + lane;
            const ull*   wp = Rt1p + lane * 17 + uw * 4;
#pragma unroll 4
            for (int j = 0; j < 16; j++) {
                ull w[4];
#pragma unroll
                for (int p = 0; p < 4; p++) w[p] = wp[p];
                wp += 32 * 17;
#pragma unroll
                for (int i = 0; i < 8; i++) {
                    float a = ap[i * 512 + j * 32];
                    ull ad; DUP2(ad, a);
#pragma unroll
                    for (int p = 0; p < 4; p++)
                        FFMA2(acc[i][p], ad, w[p]);
                }
            }
        }

        // butterfly reduction over lanes; lane l ends owning flat idx l
        {
            ull* v = &acc[0][0];
#pragma unroll
            for (int d = 16; d >= 1; d >>= 1) {
                bool hi = (lane & d) != 0;
#pragma unroll
                for (int i = 0; i < 32; i++) {
                    if (i >= d) break;
                    ull send = hi ? v[i] : v[i + d];
                    ull recv = __shfl_xor_sync(0xffffffffu, send, d);
                    ull keep = hi ? v[i + d] : v[i];
                    ADD2(v[i], keep, recv);
                }
            }
            gbuf[(bw * 8 + (lane >> 2)) * 17 + uw * 4 + (lane & 3)] = v[0];
        }
        __syncthreads();

        // ---- epilogue 1: z, r; write rh ----
        const float* gf = reinterpret_cast<const float*>(gbuf);  // row stride 34
        float gz = gf[eb * 34 + eu];
        float gr = gf[eb * 34 + 16 + eu];
        float z = fminf(fmaxf(0.2f * (xz + gz) + 0.5f, 0.f), 1.f);
        float r = fminf(fmaxf(0.2f * (xr + gr) + 0.5f, 0.f), 1.f);
        float hold = hs[eb * 512 + gu];
        g_rh[gb * UU + gu] = r * hold;
        group_barrier(group);   // all rh visible in group

        // ---- stage rh into hs ----
#pragma unroll
        for (int i = 0; i < 8; i++) {
            int id  = tid + i * 512;
            int row = id >> 7;
            int q   = id & 127;
            *reinterpret_cast<float4*>(&hs[row * 512 + q * 4]) =
                *reinterpret_cast<const float4*>(&g_rh[(b0 + row) * UU + q * 4]);
        }
        __syncthreads();

        // ======== phase 2: [32b x 512k] @ [512k x 16u], k split 2 ways ========
        ull acc2[8][4];
#pragma unroll
        for (int i = 0; i < 8; i++)
#pragma unroll
            for (int p = 0; p < 4; p++) acc2[i][p] = 0ull;

        {
            const float* ap = hs + (bw2 * 8) * 512 + kh * 256 + lane;
            const ull*   wp = Rt2p + (kh * 256 + lane) * 9 + uw2 * 4;
#pragma unroll 4
            for (int j = 0; j < 8; j++) {
                ull w[4];
#pragma unroll
                for (int p = 0; p < 4; p++) w[p] = wp[p];
                wp += 32 * 9;
#pragma unroll
                for (int i = 0; i < 8; i++) {
                    float a = ap[i * 512 + j * 32];
                    ull ad; DUP2(ad, a);
#pragma unroll
                    for (int p = 0; p < 4; p++)
                        FFMA2(acc2[i][p], ad, w[p]);
                }
            }
        }

        {
            ull* v = &acc2[0][0];
#pragma unroll
            for (int d = 16; d >= 1; d >>= 1) {
                bool hi = (lane & d) != 0;
#pragma unroll
                for (int i = 0; i < 32; i++) {
                    if (i >= d) break;
                    ull send = hi ? v[i] : v[i + d];
                    ull recv = __shfl_xor_sync(0xffffffffu, send, d);
                    ull keep = hi ? v[i + d] : v[i];
                    ADD2(v[i], keep, recv);
                }
            }
            int tile = uw2 * 4 + bw2;
            ghbuf[kh * 256 + tile * 32 + lane] = v[0];
        }
        __syncthreads();

        // ---- epilogue 2: hh, state update, attn blend ----
        {
            int bt   = eb >> 3;
            int ut   = eu >> 3;
            int tile = ut * 4 + bt;
            int li   = (eb & 7) * 4 + ((eu >> 1) & 3);
            const float* ghf = reinterpret_cast<const float*>(ghbuf);
            float gh = ghf[(tile * 32 + li) * 2 + (eu & 1)]
                     + ghf[(256 + tile * 32 + li) * 2 + (eu & 1)];
            float hh = tanhf(xh + gh);
            float hn = z * hold + (1.f - z) * hh;
            float ho = av * hn + (1.f - av) * hold;
            if (t == TT - 1) out[gb * UU + gu] = ho;
            else             hout[gb * UU + gu] = ho;
        }
        if (t < TT - 1) group_barrier(group);   // h visible before next step

        float* tmp = hin; hin = hout; hout = tmp;
    }
}

// ---------------------------------------------------------------------------
// Host launcher: 2 kernel nodes
// ---------------------------------------------------------------------------
extern "C" void kernel_launch(void* const* d_in, const int* in_sizes, int n_in,
                              void* d_out, int out_size)
{
    (void)in_sizes; (void)n_in; (void)out_size;
    const float* inputs = (const float*)d_in[0];  // [B,T,D]
    const float* attn   = (const float*)d_in[1];  // [B,T,1]
    const float* W      = (const float*)d_in[2];  // [D,3U]
    const float* R      = (const float*)d_in[3];  // [U,3U]
    const float* bias   = (const float*)d_in[4];  // [3U]
    float* out = (float*)d_out;                   // [B,U]

    static int smem_set = 0;
    if (!smem_set) {
        cudaFuncSetAttribute(gru_scan, cudaFuncAttributeMaxDynamicSharedMemorySize, SCAN_SMEM);
        smem_set = 1;
    }

    dim3 ggrid(G3 / 128, (BB * TT) / 128);
    xproj_gemm<<<ggrid, 256>>>(inputs, W, bias);

    gru_scan<<<NCTA, 512, SCAN_SMEM>>>(R, attn, out);
}